// round 14
// baseline (speedup 1.0000x reference)
#include <cuda_runtime.h>
#include <cstdint>

// ============================================================================
// Compile-time replication of np.random.default_rng(42) op-list generation.
// SeedSequence(42) -> PCG64 (setseq_128 XSL-RR 64).
// Bounded draws use numpy's 32-bit buffered Lemire path
// (buffered_bounded_lemire_uint32 via pcg64_next32 persistent buffer).
// choice(10,2,replace=False) uses FLOYD'S ALGORITHM (hash set) + _shuffle_int:
//   val8 = lemire32(8); val9 = lemire32(9);
//   idx = [val8, (val9==val8 ? 9 : val9)]; j = lemire32(1); swap if j==0.
// ============================================================================

typedef unsigned int       u32_t;
typedef unsigned long long u64_t;
typedef unsigned __int128  u128_t;

static constexpr int NW = 10;      // wires
static constexpr int NOPS = 30;    // random ops

struct CRng {
    u128_t state;
    u128_t inc;
    u32_t  ubuf;
    bool   has;

    static constexpr u128_t MULT =
        (((u128_t)0x2360ed051fc65da4ULL) << 64) | (u128_t)0x4385df649fccf645ULL;

    constexpr void step() { state = state * MULT + inc; }

    constexpr u64_t next64() {
        step();
        u64_t hi = (u64_t)(state >> 64);
        u64_t lo = (u64_t)state;
        unsigned rot = (unsigned)((u64_t)(state >> 122)) & 63u;
        u64_t v = hi ^ lo;
        return (v >> rot) | (v << ((64u - rot) & 63u));
    }

    // pcg64_next32: buffered 32-bit draws (low half first, then high half)
    constexpr u32_t next32() {
        if (has) { has = false; return ubuf; }
        u64_t n = next64();
        has = true;
        ubuf = (u32_t)(n >> 32);
        return (u32_t)n;
    }

    // numpy buffered_bounded_lemire_uint32: uniform on [0, rng] inclusive
    constexpr u32_t lemire32(u32_t rng) {
        u32_t rng_excl = rng + 1u;
        u64_t m = (u64_t)next32() * (u64_t)rng_excl;
        u32_t leftover = (u32_t)m;
        if (leftover < rng_excl) {
            u32_t threshold = (0xFFFFFFFFu - rng) % rng_excl;
            while (leftover < threshold) {
                m = (u64_t)next32() * (u64_t)rng_excl;
                leftover = (u32_t)m;
            }
        }
        return (u32_t)(m >> 32);
    }
};

struct OpsT {
    int kind[NOPS];  // 0=rx 1=ry 2=rz 3=cnot
    int a[NOPS];     // wire / control
    int b[NOPS];     // target (cnot only)
};

constexpr OpsT make_ops() {
    const u32_t INIT_A = 0x43b0d7e5u, MULT_A = 0x931e8875u;
    const u32_t INIT_B = 0x8b51f9ddu, MULT_B = 0x58f38dedu;
    const u32_t MIX_L  = 0xca01f9ddu, MIX_R  = 0x4973f715u;

    // --- SeedSequence(42).mix_entropy into 4-word pool ---
    u32_t pool[4] = {0, 0, 0, 0};
    u32_t hc = INIT_A;
    for (int i = 0; i < 4; i++) {
        u32_t v = (i < 1) ? 42u : 0u;
        v ^= hc; hc *= MULT_A; v *= hc; v ^= v >> 16;
        pool[i] = v;
    }
    for (int s = 0; s < 4; s++)
        for (int d = 0; d < 4; d++)
            if (s != d) {
                u32_t v = pool[s];
                v ^= hc; hc *= MULT_A; v *= hc; v ^= v >> 16;
                u32_t r = pool[d] * MIX_L - v * MIX_R;
                r ^= r >> 16;
                pool[d] = r;
            }

    // --- generate_state(4, uint64): 8x uint32, little-endian pairing ---
    u32_t st32[8] = {};
    {
        u32_t hb = INIT_B;
        for (int i = 0; i < 8; i++) {
            u32_t v = pool[i & 3];
            v ^= hb; hb *= MULT_B; v *= hb; v ^= v >> 16;
            st32[i] = v;
        }
    }
    u64_t sv[4] = {};
    for (int i = 0; i < 4; i++)
        sv[i] = (u64_t)st32[2 * i] | ((u64_t)st32[2 * i + 1] << 32);

    // --- PCG64 seeding: s=(sv0<<64)|sv1, i=(sv2<<64)|sv3 ---
    CRng rng{0, 0, 0, false};
    {
        u128_t initstate = (((u128_t)sv[0]) << 64) | (u128_t)sv[1];
        u128_t initseq   = (((u128_t)sv[2]) << 64) | (u128_t)sv[3];
        rng.inc = (initseq << 1) | (u128_t)1;
        rng.state = 0;
        rng.step();
        rng.state += initstate;
        rng.step();
    }

    // --- op list ---
    OpsT o = {};
    for (int i = 0; i < NOPS; i++) {
        u32_t k = rng.lemire32(3u);  // integers(0,4): 32-bit buffered Lemire
        if (k == 3u) {
            // Generator.choice(10, 2, replace=False): Floyd's algorithm
            u32_t val8 = rng.lemire32(8u);           // j = 8 draw
            u32_t val9 = rng.lemire32(9u);           // j = 9 draw
            int idx0 = (int)val8;
            int idx1 = (val9 == val8) ? 9 : (int)val9;
            // _shuffle_int(2, 1, idx): i=1, j=lemire32(1); swap if j==0
            u32_t j = rng.lemire32(1u);
            if (j == 0u) { int t = idx0; idx0 = idx1; idx1 = t; }
            o.kind[i] = 3; o.a[i] = idx0; o.b[i] = idx1;
        } else {
            o.kind[i] = (int)k;
            o.a[i] = (int)rng.lemire32(9u);  // integers(0,10)
            o.b[i] = -1;
        }
    }
    return o;
}

inline constexpr OpsT OPS = make_ops();

// ============================================================================
// Device globals (scratch; no allocations allowed)
// ============================================================================
__device__ float g_c[NOPS], g_s[NOPS];   // cos/sin(theta/2) per random op
__device__ float g_frx[2], g_fry[2];     // shared RX / RY coeffs
__device__ float g_u0[NW];               // folded MLP weights (10)
__device__ float g_bias;                 // folded MLP bias + head_b

// ============================================================================
// Prologue: gate trig + MLP folding (MLP is linear -> single affine map)
// ============================================================================
__global__ void prep_kernel(const float* __restrict__ rp,
                            const float* __restrict__ rxt,
                            const float* __restrict__ ryt,
                            const float* __restrict__ hb,
                            const float* __restrict__ w0, const float* __restrict__ b0,
                            const float* __restrict__ w1, const float* __restrict__ b1,
                            const float* __restrict__ w2, const float* __restrict__ b2,
                            const float* __restrict__ w3, const float* __restrict__ b3) {
    __shared__ float u3[16], u2[32], u1[64];
    int t = threadIdx.x;
    if (t < NOPS) {
        float a = 0.5f * rp[t];
        float s, c; sincosf(a, &s, &c);
        g_c[t] = c; g_s[t] = s;
    } else if (t == 30) {
        float a = 0.5f * rxt[0]; float s, c; sincosf(a, &s, &c);
        g_frx[0] = c; g_frx[1] = s;
    } else if (t == 31) {
        float a = 0.5f * ryt[0]; float s, c; sincosf(a, &s, &c);
        g_fry[0] = c; g_fry[1] = s;
    }
    if (t < 16) u3[t] = w3[t];
    __syncthreads();
    if (t < 32) { float acc = 0.f; for (int i = 0; i < 16; i++) acc += u3[i] * w2[i * 32 + t]; u2[t] = acc; }
    __syncthreads();
    if (t < 64) { float acc = 0.f; for (int i = 0; i < 32; i++) acc += u2[i] * w1[i * 64 + t]; u1[t] = acc; }
    __syncthreads();
    if (t < NW) { float acc = 0.f; for (int i = 0; i < 64; i++) acc += u1[i] * w0[i * NW + t]; g_u0[t] = acc; }
    if (t == 0) {
        float bias = b3[0] + hb[0];
        for (int i = 0; i < 16; i++) bias += u3[i] * b2[i];
        for (int i = 0; i < 32; i++) bias += u2[i] * b1[i];
        for (int i = 0; i < 64; i++) bias += u1[i] * b0[i];
        g_bias = bias;
    }
}

// ============================================================================
// Gate primitives: 1 warp = 1 sample. amplitude index b = (r<<5)|lane.
// wires 0..4 -> lane bits (shfl), wires 5..9 -> register index bits (FFMA only)
// ============================================================================
#define FULLM 0xffffffffu

template<int W>
__device__ __forceinline__ void gate_rx(float (&re)[32], float (&im)[32], float c, float s, int lane) {
    if constexpr (W >= 5) {
        constexpr int m = 1 << (W - 5);
        #pragma unroll
        for (int r = 0; r < 32; ++r) {
            if (!(r & m)) {
                const int r2 = r | m;
                float ar = re[r], ai = im[r], br = re[r2], bi = im[r2];
                re[r]  = c * ar + s * bi;
                im[r]  = c * ai - s * br;
                re[r2] = c * br + s * ai;
                im[r2] = c * bi - s * ar;
            }
        }
    } else {
        constexpr int m = 1 << W;
        #pragma unroll
        for (int r = 0; r < 32; ++r) {
            float pr = __shfl_xor_sync(FULLM, re[r], m);
            float pi = __shfl_xor_sync(FULLM, im[r], m);
            float ar = re[r], ai = im[r];
            re[r] = c * ar + s * pi;
            im[r] = c * ai - s * pr;
        }
    }
}

template<int W>
__device__ __forceinline__ void gate_ry(float (&re)[32], float (&im)[32], float c, float s, int lane) {
    if constexpr (W >= 5) {
        constexpr int m = 1 << (W - 5);
        #pragma unroll
        for (int r = 0; r < 32; ++r) {
            if (!(r & m)) {
                const int r2 = r | m;
                float ar = re[r], ai = im[r], br = re[r2], bi = im[r2];
                re[r]  = c * ar - s * br;
                im[r]  = c * ai - s * bi;
                re[r2] = s * ar + c * br;
                im[r2] = s * ai + c * bi;
            }
        }
    } else {
        constexpr int m = 1 << W;
        float sg = ((lane >> W) & 1) ? s : -s;
        #pragma unroll
        for (int r = 0; r < 32; ++r) {
            float pr = __shfl_xor_sync(FULLM, re[r], m);
            float pi = __shfl_xor_sync(FULLM, im[r], m);
            re[r] = c * re[r] + sg * pr;
            im[r] = c * im[r] + sg * pi;
        }
    }
}

template<int W>
__device__ __forceinline__ void gate_rz(float (&re)[32], float (&im)[32], float c, float s, int lane) {
    if constexpr (W >= 5) {
        constexpr int m = 1 << (W - 5);
        #pragma unroll
        for (int r = 0; r < 32; ++r) {
            float sg = (r & m) ? -s : s;
            float ar = re[r], ai = im[r];
            re[r] = c * ar + sg * ai;
            im[r] = c * ai - sg * ar;
        }
    } else {
        float sg = ((lane >> W) & 1) ? -s : s;
        #pragma unroll
        for (int r = 0; r < 32; ++r) {
            float ar = re[r], ai = im[r];
            re[r] = c * ar + sg * ai;
            im[r] = c * ai - sg * ar;
        }
    }
}

template<int C, int T>
__device__ __forceinline__ void gate_cnot(float (&re)[32], float (&im)[32], int lane) {
    if constexpr (C >= 5 && T >= 5) {
        constexpr int mc = 1 << (C - 5), mt = 1 << (T - 5);
        #pragma unroll
        for (int r = 0; r < 32; ++r) {
            if ((r & mc) && !(r & mt)) {
                const int r2 = r | mt;
                float t0 = re[r]; re[r] = re[r2]; re[r2] = t0;
                float t1 = im[r]; im[r] = im[r2]; im[r2] = t1;
            }
        }
    } else if constexpr (C >= 5) {  // target on lanes
        constexpr int mc = 1 << (C - 5), lt = 1 << T;
        #pragma unroll
        for (int r = 0; r < 32; ++r) {
            if (r & mc) {  // uniform across warp
                re[r] = __shfl_xor_sync(FULLM, re[r], lt);
                im[r] = __shfl_xor_sync(FULLM, im[r], lt);
            }
        }
    } else if constexpr (T >= 5) {  // control on lanes
        constexpr int mt = 1 << (T - 5);
        bool p = (lane >> C) & 1;
        #pragma unroll
        for (int r = 0; r < 32; ++r) {
            if (!(r & mt)) {
                const int r2 = r | mt;
                float a = re[r], bb = re[r2];
                re[r]  = p ? bb : a;
                re[r2] = p ? a : bb;
                float ia = im[r], ib = im[r2];
                im[r]  = p ? ib : ia;
                im[r2] = p ? ia : ib;
            }
        }
    } else {  // both on lanes
        int src = lane ^ ((((lane >> C) & 1)) << T);
        #pragma unroll
        for (int r = 0; r < 32; ++r) {
            re[r] = __shfl_sync(FULLM, re[r], src);
            im[r] = __shfl_sync(FULLM, im[r], src);
        }
    }
}

template<int I>
__device__ __forceinline__ void run_ops(float (&re)[32], float (&im)[32], int lane) {
    if constexpr (I < NOPS) {
        constexpr int K = OPS.kind[I];
        constexpr int A = OPS.a[I];
        if constexpr (K == 3) {
            constexpr int B = OPS.b[I];
            gate_cnot<A, B>(re, im, lane);
        } else {
            float c = g_c[I], s = g_s[I];
            if constexpr (K == 0)      gate_rx<A>(re, im, c, s, lane);
            else if constexpr (K == 1) gate_ry<A>(re, im, c, s, lane);
            else                       gate_rz<A>(re, im, c, s, lane);
        }
        run_ops<I + 1>(re, im, lane);
    }
}

template<int W>
__device__ __forceinline__ void run_final(float (&re)[32], float (&im)[32], int lane,
                                          float crx, float srx, float cry, float sry) {
    if constexpr (W < NW) {
        gate_rx<W>(re, im, crx, srx, lane);
        gate_ry<W>(re, im, cry, sry, lane);
        run_final<W + 1>(re, im, lane, crx, srx, cry, sry);
    }
}

__device__ __forceinline__ float wsum(float v) {
    v += __shfl_xor_sync(FULLM, v, 16);
    v += __shfl_xor_sync(FULLM, v, 8);
    v += __shfl_xor_sync(FULLM, v, 4);
    v += __shfl_xor_sync(FULLM, v, 2);
    v += __shfl_xor_sync(FULLM, v, 1);
    return v;
}

// ============================================================================
// Main kernel: one warp per batch element, full state in registers.
// ============================================================================
__global__ void __launch_bounds__(128)
qsim_kernel(const float* __restrict__ x, const float* __restrict__ head_w,
            float* __restrict__ out, int bsz) {
    int warp = (int)((blockIdx.x * blockDim.x + threadIdx.x) >> 5);
    int lane = (int)(threadIdx.x & 31);
    if (warp >= bsz) return;

    // ---- encoder: product state of RY(x_w)|0> ----
    const float* xr = x + warp * NW;
    float xq[NW], cs[NW], sn[NW];
    #pragma unroll
    for (int w = 0; w < NW; ++w) {
        xq[w] = xr[w];
        sincosf(0.5f * xq[w], &sn[w], &cs[w]);
    }
    float pl = 1.0f;
    #pragma unroll
    for (int w = 0; w < 5; ++w) pl *= ((lane >> w) & 1) ? sn[w] : cs[w];

    float re[32], im[32];
    #pragma unroll
    for (int r = 0; r < 32; ++r) {
        float pr = pl;
        #pragma unroll
        for (int j = 0; j < 5; ++j) pr *= ((r >> j) & 1) ? sn[5 + j] : cs[5 + j];
        re[r] = pr;
        im[r] = 0.0f;
    }

    // ---- 30 frozen random gates ----
    run_ops<0>(re, im, lane);

    // ---- shared RX then RY on every wire ----
    {
        float crx = g_frx[0], srx = g_frx[1];
        float cry = g_fry[0], sry = g_fry[1];
        run_final<0>(re, im, lane, crx, srx, cry, sry);
    }

    // ---- measurement: <Z_w> ----
    float tot = 0.f, z5 = 0.f, z6 = 0.f, z7 = 0.f, z8 = 0.f, z9 = 0.f;
    #pragma unroll
    for (int r = 0; r < 32; ++r) {
        float p = re[r] * re[r] + im[r] * im[r];
        tot += p;
        z5 += (r & 1)  ? -p : p;
        z6 += (r & 2)  ? -p : p;
        z7 += (r & 4)  ? -p : p;
        z8 += (r & 8)  ? -p : p;
        z9 += (r & 16) ? -p : p;
    }
    z5 = wsum(z5); z6 = wsum(z6); z7 = wsum(z7); z8 = wsum(z8); z9 = wsum(z9);
    float z0 = wsum(((lane >> 0) & 1) ? -tot : tot);
    float z1 = wsum(((lane >> 1) & 1) ? -tot : tot);
    float z2 = wsum(((lane >> 2) & 1) ? -tot : tot);
    float z3 = wsum(((lane >> 3) & 1) ? -tot : tot);
    float z4 = wsum(((lane >> 4) & 1) ? -tot : tot);

    if (lane == 0) {
        float q = g_bias;
        q += z0 * head_w[0] + z1 * head_w[1] + z2 * head_w[2] + z3 * head_w[3] + z4 * head_w[4];
        q += z5 * head_w[5] + z6 * head_w[6] + z7 * head_w[7] + z8 * head_w[8] + z9 * head_w[9];
        #pragma unroll
        for (int w = 0; w < NW; ++w) q += xq[w] * g_u0[w];
        out[warp] = q;
    }
}

// ============================================================================
// Launch
// ============================================================================
extern "C" void kernel_launch(void* const* d_in, const int* in_sizes, int n_in,
                              void* d_out, int out_size) {
    const float* x   = (const float*)d_in[0];
    const float* rp  = (const float*)d_in[1];
    const float* rxt = (const float*)d_in[2];
    const float* ryt = (const float*)d_in[3];
    const float* hw  = (const float*)d_in[4];
    const float* hb  = (const float*)d_in[5];
    const float* w0  = (const float*)d_in[6];
    const float* b0  = (const float*)d_in[7];
    const float* w1  = (const float*)d_in[8];
    const float* b1  = (const float*)d_in[9];
    const float* w2  = (const float*)d_in[10];
    const float* b2  = (const float*)d_in[11];
    const float* w3  = (const float*)d_in[12];
    const float* b3  = (const float*)d_in[13];

    int bsz = in_sizes[0] / NW;

    prep_kernel<<<1, 64>>>(rp, rxt, ryt, hb, w0, b0, w1, b1, w2, b2, w3, b3);

    const int warps_per_block = 4;  // 128 threads
    int blocks = (bsz + warps_per_block - 1) / warps_per_block;
    qsim_kernel<<<blocks, 128>>>(x, hw, (float*)d_out, bsz);
}

// round 15
// speedup vs baseline: 1.0115x; 1.0115x over previous
#include <cuda_runtime.h>
#include <cstdint>

// ============================================================================
// Compile-time replication of np.random.default_rng(42) op-list generation.
// SeedSequence(42) -> PCG64 (setseq_128 XSL-RR 64).
// Bounded draws use numpy's 32-bit buffered Lemire path
// (buffered_bounded_lemire_uint32 via pcg64_next32 persistent buffer).
// choice(10,2,replace=False) uses FLOYD'S ALGORITHM (hash set) + _shuffle_int:
//   val8 = lemire32(8); val9 = lemire32(9);
//   idx = [val8, (val9==val8 ? 9 : val9)]; j = lemire32(1); swap if j==0.
// ============================================================================

typedef unsigned int       u32_t;
typedef unsigned long long u64_t;
typedef unsigned __int128  u128_t;

static constexpr int NW = 10;      // wires
static constexpr int NOPS = 30;    // random ops

struct CRng {
    u128_t state;
    u128_t inc;
    u32_t  ubuf;
    bool   has;

    static constexpr u128_t MULT =
        (((u128_t)0x2360ed051fc65da4ULL) << 64) | (u128_t)0x4385df649fccf645ULL;

    constexpr void step() { state = state * MULT + inc; }

    constexpr u64_t next64() {
        step();
        u64_t hi = (u64_t)(state >> 64);
        u64_t lo = (u64_t)state;
        unsigned rot = (unsigned)((u64_t)(state >> 122)) & 63u;
        u64_t v = hi ^ lo;
        return (v >> rot) | (v << ((64u - rot) & 63u));
    }

    // pcg64_next32: buffered 32-bit draws (low half first, then high half)
    constexpr u32_t next32() {
        if (has) { has = false; return ubuf; }
        u64_t n = next64();
        has = true;
        ubuf = (u32_t)(n >> 32);
        return (u32_t)n;
    }

    // numpy buffered_bounded_lemire_uint32: uniform on [0, rng] inclusive
    constexpr u32_t lemire32(u32_t rng) {
        u32_t rng_excl = rng + 1u;
        u64_t m = (u64_t)next32() * (u64_t)rng_excl;
        u32_t leftover = (u32_t)m;
        if (leftover < rng_excl) {
            u32_t threshold = (0xFFFFFFFFu - rng) % rng_excl;
            while (leftover < threshold) {
                m = (u64_t)next32() * (u64_t)rng_excl;
                leftover = (u32_t)m;
            }
        }
        return (u32_t)(m >> 32);
    }
};

struct OpsT {
    int kind[NOPS];  // 0=rx 1=ry 2=rz 3=cnot
    int a[NOPS];     // wire / control
    int b[NOPS];     // target (cnot only)
};

constexpr OpsT make_ops() {
    const u32_t INIT_A = 0x43b0d7e5u, MULT_A = 0x931e8875u;
    const u32_t INIT_B = 0x8b51f9ddu, MULT_B = 0x58f38dedu;
    const u32_t MIX_L  = 0xca01f9ddu, MIX_R  = 0x4973f715u;

    // --- SeedSequence(42).mix_entropy into 4-word pool ---
    u32_t pool[4] = {0, 0, 0, 0};
    u32_t hc = INIT_A;
    for (int i = 0; i < 4; i++) {
        u32_t v = (i < 1) ? 42u : 0u;
        v ^= hc; hc *= MULT_A; v *= hc; v ^= v >> 16;
        pool[i] = v;
    }
    for (int s = 0; s < 4; s++)
        for (int d = 0; d < 4; d++)
            if (s != d) {
                u32_t v = pool[s];
                v ^= hc; hc *= MULT_A; v *= hc; v ^= v >> 16;
                u32_t r = pool[d] * MIX_L - v * MIX_R;
                r ^= r >> 16;
                pool[d] = r;
            }

    // --- generate_state(4, uint64): 8x uint32, little-endian pairing ---
    u32_t st32[8] = {};
    {
        u32_t hb = INIT_B;
        for (int i = 0; i < 8; i++) {
            u32_t v = pool[i & 3];
            v ^= hb; hb *= MULT_B; v *= hb; v ^= v >> 16;
            st32[i] = v;
        }
    }
    u64_t sv[4] = {};
    for (int i = 0; i < 4; i++)
        sv[i] = (u64_t)st32[2 * i] | ((u64_t)st32[2 * i + 1] << 32);

    // --- PCG64 seeding: s=(sv0<<64)|sv1, i=(sv2<<64)|sv3 ---
    CRng rng{0, 0, 0, false};
    {
        u128_t initstate = (((u128_t)sv[0]) << 64) | (u128_t)sv[1];
        u128_t initseq   = (((u128_t)sv[2]) << 64) | (u128_t)sv[3];
        rng.inc = (initseq << 1) | (u128_t)1;
        rng.state = 0;
        rng.step();
        rng.state += initstate;
        rng.step();
    }

    // --- op list ---
    OpsT o = {};
    for (int i = 0; i < NOPS; i++) {
        u32_t k = rng.lemire32(3u);  // integers(0,4): 32-bit buffered Lemire
        if (k == 3u) {
            // Generator.choice(10, 2, replace=False): Floyd's algorithm
            u32_t val8 = rng.lemire32(8u);           // j = 8 draw
            u32_t val9 = rng.lemire32(9u);           // j = 9 draw
            int idx0 = (int)val8;
            int idx1 = (val9 == val8) ? 9 : (int)val9;
            // _shuffle_int(2, 1, idx): i=1, j=lemire32(1); swap if j==0
            u32_t j = rng.lemire32(1u);
            if (j == 0u) { int t = idx0; idx0 = idx1; idx1 = t; }
            o.kind[i] = 3; o.a[i] = idx0; o.b[i] = idx1;
        } else {
            o.kind[i] = (int)k;
            o.a[i] = (int)rng.lemire32(9u);  // integers(0,10)
            o.b[i] = -1;
        }
    }
    return o;
}

inline constexpr OpsT OPS = make_ops();

// ============================================================================
// Device globals (scratch; no allocations allowed)
// ============================================================================
__device__ float g_c[NOPS], g_s[NOPS];   // cos/sin(theta/2) per random op
__device__ float g_frx[2], g_fry[2];     // shared RX / RY coeffs
__device__ float g_u0[NW];               // folded MLP weights (10)
__device__ float g_bias;                 // folded MLP bias + head_b

// ============================================================================
// Prologue: gate trig + MLP folding (MLP is linear -> single affine map)
// ============================================================================
__global__ void prep_kernel(const float* __restrict__ rp,
                            const float* __restrict__ rxt,
                            const float* __restrict__ ryt,
                            const float* __restrict__ hb,
                            const float* __restrict__ w0, const float* __restrict__ b0,
                            const float* __restrict__ w1, const float* __restrict__ b1,
                            const float* __restrict__ w2, const float* __restrict__ b2,
                            const float* __restrict__ w3, const float* __restrict__ b3) {
    __shared__ float u3[16], u2[32], u1[64];
    int t = threadIdx.x;
    if (t < NOPS) {
        float a = 0.5f * rp[t];
        float s, c; sincosf(a, &s, &c);
        g_c[t] = c; g_s[t] = s;
    } else if (t == 30) {
        float a = 0.5f * rxt[0]; float s, c; sincosf(a, &s, &c);
        g_frx[0] = c; g_frx[1] = s;
    } else if (t == 31) {
        float a = 0.5f * ryt[0]; float s, c; sincosf(a, &s, &c);
        g_fry[0] = c; g_fry[1] = s;
    }
    if (t < 16) u3[t] = w3[t];
    __syncthreads();
    if (t < 32) { float acc = 0.f; for (int i = 0; i < 16; i++) acc += u3[i] * w2[i * 32 + t]; u2[t] = acc; }
    __syncthreads();
    if (t < 64) { float acc = 0.f; for (int i = 0; i < 32; i++) acc += u2[i] * w1[i * 64 + t]; u1[t] = acc; }
    __syncthreads();
    if (t < NW) { float acc = 0.f; for (int i = 0; i < 64; i++) acc += u1[i] * w0[i * NW + t]; g_u0[t] = acc; }
    if (t == 0) {
        float bias = b3[0] + hb[0];
        for (int i = 0; i < 16; i++) bias += u3[i] * b2[i];
        for (int i = 0; i < 32; i++) bias += u2[i] * b1[i];
        for (int i = 0; i < 64; i++) bias += u1[i] * b0[i];
        g_bias = bias;
    }
}

// ============================================================================
// Gate primitives: 1 warp = 1 sample. amplitude index b = (r<<5)|lane.
// wires 0..4 -> lane bits (shfl), wires 5..9 -> register index bits (FFMA only)
// ============================================================================
#define FULLM 0xffffffffu

template<int W>
__device__ __forceinline__ void gate_rx(float (&re)[32], float (&im)[32], float c, float s, int lane) {
    if constexpr (W >= 5) {
        constexpr int m = 1 << (W - 5);
        #pragma unroll
        for (int r = 0; r < 32; ++r) {
            if (!(r & m)) {
                const int r2 = r | m;
                float ar = re[r], ai = im[r], br = re[r2], bi = im[r2];
                re[r]  = c * ar + s * bi;
                im[r]  = c * ai - s * br;
                re[r2] = c * br + s * ai;
                im[r2] = c * bi - s * ar;
            }
        }
    } else {
        constexpr int m = 1 << W;
        #pragma unroll
        for (int r = 0; r < 32; ++r) {
            float pr = __shfl_xor_sync(FULLM, re[r], m);
            float pi = __shfl_xor_sync(FULLM, im[r], m);
            float ar = re[r], ai = im[r];
            re[r] = c * ar + s * pi;
            im[r] = c * ai - s * pr;
        }
    }
}

template<int W>
__device__ __forceinline__ void gate_ry(float (&re)[32], float (&im)[32], float c, float s, int lane) {
    if constexpr (W >= 5) {
        constexpr int m = 1 << (W - 5);
        #pragma unroll
        for (int r = 0; r < 32; ++r) {
            if (!(r & m)) {
                const int r2 = r | m;
                float ar = re[r], ai = im[r], br = re[r2], bi = im[r2];
                re[r]  = c * ar - s * br;
                im[r]  = c * ai - s * bi;
                re[r2] = s * ar + c * br;
                im[r2] = s * ai + c * bi;
            }
        }
    } else {
        constexpr int m = 1 << W;
        float sg = ((lane >> W) & 1) ? s : -s;
        #pragma unroll
        for (int r = 0; r < 32; ++r) {
            float pr = __shfl_xor_sync(FULLM, re[r], m);
            float pi = __shfl_xor_sync(FULLM, im[r], m);
            re[r] = c * re[r] + sg * pr;
            im[r] = c * im[r] + sg * pi;
        }
    }
}

template<int W>
__device__ __forceinline__ void gate_rz(float (&re)[32], float (&im)[32], float c, float s, int lane) {
    if constexpr (W >= 5) {
        constexpr int m = 1 << (W - 5);
        #pragma unroll
        for (int r = 0; r < 32; ++r) {
            float sg = (r & m) ? -s : s;
            float ar = re[r], ai = im[r];
            re[r] = c * ar + sg * ai;
            im[r] = c * ai - sg * ar;
        }
    } else {
        float sg = ((lane >> W) & 1) ? -s : s;
        #pragma unroll
        for (int r = 0; r < 32; ++r) {
            float ar = re[r], ai = im[r];
            re[r] = c * ar + sg * ai;
            im[r] = c * ai - sg * ar;
        }
    }
}

template<int C, int T>
__device__ __forceinline__ void gate_cnot(float (&re)[32], float (&im)[32], int lane) {
    if constexpr (C >= 5 && T >= 5) {
        constexpr int mc = 1 << (C - 5), mt = 1 << (T - 5);
        #pragma unroll
        for (int r = 0; r < 32; ++r) {
            if ((r & mc) && !(r & mt)) {
                const int r2 = r | mt;
                float t0 = re[r]; re[r] = re[r2]; re[r2] = t0;
                float t1 = im[r]; im[r] = im[r2]; im[r2] = t1;
            }
        }
    } else if constexpr (C >= 5) {  // target on lanes
        constexpr int mc = 1 << (C - 5), lt = 1 << T;
        #pragma unroll
        for (int r = 0; r < 32; ++r) {
            if (r & mc) {  // uniform across warp
                re[r] = __shfl_xor_sync(FULLM, re[r], lt);
                im[r] = __shfl_xor_sync(FULLM, im[r], lt);
            }
        }
    } else if constexpr (T >= 5) {  // control on lanes
        constexpr int mt = 1 << (T - 5);
        bool p = (lane >> C) & 1;
        #pragma unroll
        for (int r = 0; r < 32; ++r) {
            if (!(r & mt)) {
                const int r2 = r | mt;
                float a = re[r], bb = re[r2];
                re[r]  = p ? bb : a;
                re[r2] = p ? a : bb;
                float ia = im[r], ib = im[r2];
                im[r]  = p ? ib : ia;
                im[r2] = p ? ia : ib;
            }
        }
    } else {  // both on lanes
        int src = lane ^ ((((lane >> C) & 1)) << T);
        #pragma unroll
        for (int r = 0; r < 32; ++r) {
            re[r] = __shfl_sync(FULLM, re[r], src);
            im[r] = __shfl_sync(FULLM, im[r], src);
        }
    }
}

template<int I>
__device__ __forceinline__ void run_ops(float (&re)[32], float (&im)[32], int lane) {
    if constexpr (I < NOPS) {
        constexpr int K = OPS.kind[I];
        constexpr int A = OPS.a[I];
        if constexpr (K == 3) {
            constexpr int B = OPS.b[I];
            gate_cnot<A, B>(re, im, lane);
        } else {
            float c = g_c[I], s = g_s[I];
            if constexpr (K == 0)      gate_rx<A>(re, im, c, s, lane);
            else if constexpr (K == 1) gate_ry<A>(re, im, c, s, lane);
            else                       gate_rz<A>(re, im, c, s, lane);
        }
        run_ops<I + 1>(re, im, lane);
    }
}

template<int W>
__device__ __forceinline__ void run_final(float (&re)[32], float (&im)[32], int lane,
                                          float crx, float srx, float cry, float sry) {
    if constexpr (W < NW) {
        gate_rx<W>(re, im, crx, srx, lane);
        gate_ry<W>(re, im, cry, sry, lane);
        run_final<W + 1>(re, im, lane, crx, srx, cry, sry);
    }
}

__device__ __forceinline__ float wsum(float v) {
    v += __shfl_xor_sync(FULLM, v, 16);
    v += __shfl_xor_sync(FULLM, v, 8);
    v += __shfl_xor_sync(FULLM, v, 4);
    v += __shfl_xor_sync(FULLM, v, 2);
    v += __shfl_xor_sync(FULLM, v, 1);
    return v;
}

// ============================================================================
// Main kernel: one warp per batch element, full state in registers.
// ============================================================================
__global__ void __launch_bounds__(128)
qsim_kernel(const float* __restrict__ x, const float* __restrict__ head_w,
            float* __restrict__ out, int bsz) {
    int warp = (int)((blockIdx.x * blockDim.x + threadIdx.x) >> 5);
    int lane = (int)(threadIdx.x & 31);
    if (warp >= bsz) return;

    // ---- encoder: product state of RY(x_w)|0> ----
    const float* xr = x + warp * NW;
    float xq[NW], cs[NW], sn[NW];
    #pragma unroll
    for (int w = 0; w < NW; ++w) {
        xq[w] = xr[w];
        sincosf(0.5f * xq[w], &sn[w], &cs[w]);
    }
    float pl = 1.0f;
    #pragma unroll
    for (int w = 0; w < 5; ++w) pl *= ((lane >> w) & 1) ? sn[w] : cs[w];

    float re[32], im[32];
    #pragma unroll
    for (int r = 0; r < 32; ++r) {
        float pr = pl;
        #pragma unroll
        for (int j = 0; j < 5; ++j) pr *= ((r >> j) & 1) ? sn[5 + j] : cs[5 + j];
        re[r] = pr;
        im[r] = 0.0f;
    }

    // ---- 30 frozen random gates ----
    run_ops<0>(re, im, lane);

    // ---- shared RX then RY on every wire ----
    {
        float crx = g_frx[0], srx = g_frx[1];
        float cry = g_fry[0], sry = g_fry[1];
        run_final<0>(re, im, lane, crx, srx, cry, sry);
    }

    // ---- measurement: <Z_w> ----
    float tot = 0.f, z5 = 0.f, z6 = 0.f, z7 = 0.f, z8 = 0.f, z9 = 0.f;
    #pragma unroll
    for (int r = 0; r < 32; ++r) {
        float p = re[r] * re[r] + im[r] * im[r];
        tot += p;
        z5 += (r & 1)  ? -p : p;
        z6 += (r & 2)  ? -p : p;
        z7 += (r & 4)  ? -p : p;
        z8 += (r & 8)  ? -p : p;
        z9 += (r & 16) ? -p : p;
    }
    z5 = wsum(z5); z6 = wsum(z6); z7 = wsum(z7); z8 = wsum(z8); z9 = wsum(z9);
    float z0 = wsum(((lane >> 0) & 1) ? -tot : tot);
    float z1 = wsum(((lane >> 1) & 1) ? -tot : tot);
    float z2 = wsum(((lane >> 2) & 1) ? -tot : tot);
    float z3 = wsum(((lane >> 3) & 1) ? -tot : tot);
    float z4 = wsum(((lane >> 4) & 1) ? -tot : tot);

    if (lane == 0) {
        float q = g_bias;
        q += z0 * head_w[0] + z1 * head_w[1] + z2 * head_w[2] + z3 * head_w[3] + z4 * head_w[4];
        q += z5 * head_w[5] + z6 * head_w[6] + z7 * head_w[7] + z8 * head_w[8] + z9 * head_w[9];
        #pragma unroll
        for (int w = 0; w < NW; ++w) q += xq[w] * g_u0[w];
        out[warp] = q;
    }
}

// ============================================================================
// Launch
// ============================================================================
extern "C" void kernel_launch(void* const* d_in, const int* in_sizes, int n_in,
                              void* d_out, int out_size) {
    const float* x   = (const float*)d_in[0];
    const float* rp  = (const float*)d_in[1];
    const float* rxt = (const float*)d_in[2];
    const float* ryt = (const float*)d_in[3];
    const float* hw  = (const float*)d_in[4];
    const float* hb  = (const float*)d_in[5];
    const float* w0  = (const float*)d_in[6];
    const float* b0  = (const float*)d_in[7];
    const float* w1  = (const float*)d_in[8];
    const float* b1  = (const float*)d_in[9];
    const float* w2  = (const float*)d_in[10];
    const float* b2  = (const float*)d_in[11];
    const float* w3  = (const float*)d_in[12];
    const float* b3  = (const float*)d_in[13];

    int bsz = in_sizes[0] / NW;

    prep_kernel<<<1, 64>>>(rp, rxt, ryt, hb, w0, b0, w1, b1, w2, b2, w3, b3);

    const int warps_per_block = 4;  // 128 threads
    int blocks = (bsz + warps_per_block - 1) / warps_per_block;
    qsim_kernel<<<blocks, 128>>>(x, hw, (float*)d_out, bsz);
}

// round 16
// speedup vs baseline: 1.0149x; 1.0034x over previous
#include <cuda_runtime.h>
#include <cstdint>

// ============================================================================
// Compile-time replication of np.random.default_rng(42) op-list generation.
// SeedSequence(42) -> PCG64 (setseq_128 XSL-RR 64).
// Bounded draws use numpy's 32-bit buffered Lemire path
// (buffered_bounded_lemire_uint32 via pcg64_next32 persistent buffer).
// choice(10,2,replace=False) uses FLOYD'S ALGORITHM (hash set) + _shuffle_int:
//   val8 = lemire32(8); val9 = lemire32(9);
//   idx = [val8, (val9==val8 ? 9 : val9)]; j = lemire32(1); swap if j==0.
// ============================================================================

typedef unsigned int       u32_t;
typedef unsigned long long u64_t;
typedef unsigned __int128  u128_t;

static constexpr int NW = 10;      // wires
static constexpr int NOPS = 30;    // random ops

struct CRng {
    u128_t state;
    u128_t inc;
    u32_t  ubuf;
    bool   has;

    static constexpr u128_t MULT =
        (((u128_t)0x2360ed051fc65da4ULL) << 64) | (u128_t)0x4385df649fccf645ULL;

    constexpr void step() { state = state * MULT + inc; }

    constexpr u64_t next64() {
        step();
        u64_t hi = (u64_t)(state >> 64);
        u64_t lo = (u64_t)state;
        unsigned rot = (unsigned)((u64_t)(state >> 122)) & 63u;
        u64_t v = hi ^ lo;
        return (v >> rot) | (v << ((64u - rot) & 63u));
    }

    // pcg64_next32: buffered 32-bit draws (low half first, then high half)
    constexpr u32_t next32() {
        if (has) { has = false; return ubuf; }
        u64_t n = next64();
        has = true;
        ubuf = (u32_t)(n >> 32);
        return (u32_t)n;
    }

    // numpy buffered_bounded_lemire_uint32: uniform on [0, rng] inclusive
    constexpr u32_t lemire32(u32_t rng) {
        u32_t rng_excl = rng + 1u;
        u64_t m = (u64_t)next32() * (u64_t)rng_excl;
        u32_t leftover = (u32_t)m;
        if (leftover < rng_excl) {
            u32_t threshold = (0xFFFFFFFFu - rng) % rng_excl;
            while (leftover < threshold) {
                m = (u64_t)next32() * (u64_t)rng_excl;
                leftover = (u32_t)m;
            }
        }
        return (u32_t)(m >> 32);
    }
};

struct OpsT {
    int kind[NOPS];  // 0=rx 1=ry 2=rz 3=cnot
    int a[NOPS];     // wire / control
    int b[NOPS];     // target (cnot only)
};

constexpr OpsT make_ops() {
    const u32_t INIT_A = 0x43b0d7e5u, MULT_A = 0x931e8875u;
    const u32_t INIT_B = 0x8b51f9ddu, MULT_B = 0x58f38dedu;
    const u32_t MIX_L  = 0xca01f9ddu, MIX_R  = 0x4973f715u;

    // --- SeedSequence(42).mix_entropy into 4-word pool ---
    u32_t pool[4] = {0, 0, 0, 0};
    u32_t hc = INIT_A;
    for (int i = 0; i < 4; i++) {
        u32_t v = (i < 1) ? 42u : 0u;
        v ^= hc; hc *= MULT_A; v *= hc; v ^= v >> 16;
        pool[i] = v;
    }
    for (int s = 0; s < 4; s++)
        for (int d = 0; d < 4; d++)
            if (s != d) {
                u32_t v = pool[s];
                v ^= hc; hc *= MULT_A; v *= hc; v ^= v >> 16;
                u32_t r = pool[d] * MIX_L - v * MIX_R;
                r ^= r >> 16;
                pool[d] = r;
            }

    // --- generate_state(4, uint64): 8x uint32, little-endian pairing ---
    u32_t st32[8] = {};
    {
        u32_t hb = INIT_B;
        for (int i = 0; i < 8; i++) {
            u32_t v = pool[i & 3];
            v ^= hb; hb *= MULT_B; v *= hb; v ^= v >> 16;
            st32[i] = v;
        }
    }
    u64_t sv[4] = {};
    for (int i = 0; i < 4; i++)
        sv[i] = (u64_t)st32[2 * i] | ((u64_t)st32[2 * i + 1] << 32);

    // --- PCG64 seeding: s=(sv0<<64)|sv1, i=(sv2<<64)|sv3 ---
    CRng rng{0, 0, 0, false};
    {
        u128_t initstate = (((u128_t)sv[0]) << 64) | (u128_t)sv[1];
        u128_t initseq   = (((u128_t)sv[2]) << 64) | (u128_t)sv[3];
        rng.inc = (initseq << 1) | (u128_t)1;
        rng.state = 0;
        rng.step();
        rng.state += initstate;
        rng.step();
    }

    // --- op list ---
    OpsT o = {};
    for (int i = 0; i < NOPS; i++) {
        u32_t k = rng.lemire32(3u);  // integers(0,4): 32-bit buffered Lemire
        if (k == 3u) {
            // Generator.choice(10, 2, replace=False): Floyd's algorithm
            u32_t val8 = rng.lemire32(8u);           // j = 8 draw
            u32_t val9 = rng.lemire32(9u);           // j = 9 draw
            int idx0 = (int)val8;
            int idx1 = (val9 == val8) ? 9 : (int)val9;
            // _shuffle_int(2, 1, idx): i=1, j=lemire32(1); swap if j==0
            u32_t j = rng.lemire32(1u);
            if (j == 0u) { int t = idx0; idx0 = idx1; idx1 = t; }
            o.kind[i] = 3; o.a[i] = idx0; o.b[i] = idx1;
        } else {
            o.kind[i] = (int)k;
            o.a[i] = (int)rng.lemire32(9u);  // integers(0,10)
            o.b[i] = -1;
        }
    }
    return o;
}

inline constexpr OpsT OPS = make_ops();

// ============================================================================
// Device globals (scratch; no allocations allowed)
// ============================================================================
__device__ float g_c[NOPS], g_s[NOPS];   // cos/sin(theta/2) per random op
__device__ float g_frx[2], g_fry[2];     // shared RX / RY coeffs
__device__ float g_u0[NW];               // folded MLP weights (10)
__device__ float g_bias;                 // folded MLP bias + head_b

// ============================================================================
// Prologue: gate trig + MLP folding (MLP is linear -> single affine map)
// ============================================================================
__global__ void prep_kernel(const float* __restrict__ rp,
                            const float* __restrict__ rxt,
                            const float* __restrict__ ryt,
                            const float* __restrict__ hb,
                            const float* __restrict__ w0, const float* __restrict__ b0,
                            const float* __restrict__ w1, const float* __restrict__ b1,
                            const float* __restrict__ w2, const float* __restrict__ b2,
                            const float* __restrict__ w3, const float* __restrict__ b3) {
    __shared__ float u3[16], u2[32], u1[64];
    int t = threadIdx.x;
    if (t < NOPS) {
        float a = 0.5f * rp[t];
        float s, c; sincosf(a, &s, &c);
        g_c[t] = c; g_s[t] = s;
    } else if (t == 30) {
        float a = 0.5f * rxt[0]; float s, c; sincosf(a, &s, &c);
        g_frx[0] = c; g_frx[1] = s;
    } else if (t == 31) {
        float a = 0.5f * ryt[0]; float s, c; sincosf(a, &s, &c);
        g_fry[0] = c; g_fry[1] = s;
    }
    if (t < 16) u3[t] = w3[t];
    __syncthreads();
    if (t < 32) { float acc = 0.f; for (int i = 0; i < 16; i++) acc += u3[i] * w2[i * 32 + t]; u2[t] = acc; }
    __syncthreads();
    if (t < 64) { float acc = 0.f; for (int i = 0; i < 32; i++) acc += u2[i] * w1[i * 64 + t]; u1[t] = acc; }
    __syncthreads();
    if (t < NW) { float acc = 0.f; for (int i = 0; i < 64; i++) acc += u1[i] * w0[i * NW + t]; g_u0[t] = acc; }
    if (t == 0) {
        float bias = b3[0] + hb[0];
        for (int i = 0; i < 16; i++) bias += u3[i] * b2[i];
        for (int i = 0; i < 32; i++) bias += u2[i] * b1[i];
        for (int i = 0; i < 64; i++) bias += u1[i] * b0[i];
        g_bias = bias;
    }
}

// ============================================================================
// Gate primitives: 1 warp = 1 sample. amplitude index b = (r<<5)|lane.
// wires 0..4 -> lane bits (shfl), wires 5..9 -> register index bits (FFMA only)
// ============================================================================
#define FULLM 0xffffffffu

template<int W>
__device__ __forceinline__ void gate_rx(float (&re)[32], float (&im)[32], float c, float s, int lane) {
    if constexpr (W >= 5) {
        constexpr int m = 1 << (W - 5);
        #pragma unroll
        for (int r = 0; r < 32; ++r) {
            if (!(r & m)) {
                const int r2 = r | m;
                float ar = re[r], ai = im[r], br = re[r2], bi = im[r2];
                re[r]  = c * ar + s * bi;
                im[r]  = c * ai - s * br;
                re[r2] = c * br + s * ai;
                im[r2] = c * bi - s * ar;
            }
        }
    } else {
        constexpr int m = 1 << W;
        #pragma unroll
        for (int r = 0; r < 32; ++r) {
            float pr = __shfl_xor_sync(FULLM, re[r], m);
            float pi = __shfl_xor_sync(FULLM, im[r], m);
            float ar = re[r], ai = im[r];
            re[r] = c * ar + s * pi;
            im[r] = c * ai - s * pr;
        }
    }
}

template<int W>
__device__ __forceinline__ void gate_ry(float (&re)[32], float (&im)[32], float c, float s, int lane) {
    if constexpr (W >= 5) {
        constexpr int m = 1 << (W - 5);
        #pragma unroll
        for (int r = 0; r < 32; ++r) {
            if (!(r & m)) {
                const int r2 = r | m;
                float ar = re[r], ai = im[r], br = re[r2], bi = im[r2];
                re[r]  = c * ar - s * br;
                im[r]  = c * ai - s * bi;
                re[r2] = s * ar + c * br;
                im[r2] = s * ai + c * bi;
            }
        }
    } else {
        constexpr int m = 1 << W;
        float sg = ((lane >> W) & 1) ? s : -s;
        #pragma unroll
        for (int r = 0; r < 32; ++r) {
            float pr = __shfl_xor_sync(FULLM, re[r], m);
            float pi = __shfl_xor_sync(FULLM, im[r], m);
            re[r] = c * re[r] + sg * pr;
            im[r] = c * im[r] + sg * pi;
        }
    }
}

template<int W>
__device__ __forceinline__ void gate_rz(float (&re)[32], float (&im)[32], float c, float s, int lane) {
    if constexpr (W >= 5) {
        constexpr int m = 1 << (W - 5);
        #pragma unroll
        for (int r = 0; r < 32; ++r) {
            float sg = (r & m) ? -s : s;
            float ar = re[r], ai = im[r];
            re[r] = c * ar + sg * ai;
            im[r] = c * ai - sg * ar;
        }
    } else {
        float sg = ((lane >> W) & 1) ? -s : s;
        #pragma unroll
        for (int r = 0; r < 32; ++r) {
            float ar = re[r], ai = im[r];
            re[r] = c * ar + sg * ai;
            im[r] = c * ai - sg * ar;
        }
    }
}

template<int C, int T>
__device__ __forceinline__ void gate_cnot(float (&re)[32], float (&im)[32], int lane) {
    if constexpr (C >= 5 && T >= 5) {
        constexpr int mc = 1 << (C - 5), mt = 1 << (T - 5);
        #pragma unroll
        for (int r = 0; r < 32; ++r) {
            if ((r & mc) && !(r & mt)) {
                const int r2 = r | mt;
                float t0 = re[r]; re[r] = re[r2]; re[r2] = t0;
                float t1 = im[r]; im[r] = im[r2]; im[r2] = t1;
            }
        }
    } else if constexpr (C >= 5) {  // target on lanes
        constexpr int mc = 1 << (C - 5), lt = 1 << T;
        #pragma unroll
        for (int r = 0; r < 32; ++r) {
            if (r & mc) {  // uniform across warp
                re[r] = __shfl_xor_sync(FULLM, re[r], lt);
                im[r] = __shfl_xor_sync(FULLM, im[r], lt);
            }
        }
    } else if constexpr (T >= 5) {  // control on lanes
        constexpr int mt = 1 << (T - 5);
        bool p = (lane >> C) & 1;
        #pragma unroll
        for (int r = 0; r < 32; ++r) {
            if (!(r & mt)) {
                const int r2 = r | mt;
                float a = re[r], bb = re[r2];
                re[r]  = p ? bb : a;
                re[r2] = p ? a : bb;
                float ia = im[r], ib = im[r2];
                im[r]  = p ? ib : ia;
                im[r2] = p ? ia : ib;
            }
        }
    } else {  // both on lanes
        int src = lane ^ ((((lane >> C) & 1)) << T);
        #pragma unroll
        for (int r = 0; r < 32; ++r) {
            re[r] = __shfl_sync(FULLM, re[r], src);
            im[r] = __shfl_sync(FULLM, im[r], src);
        }
    }
}

template<int I>
__device__ __forceinline__ void run_ops(float (&re)[32], float (&im)[32], int lane) {
    if constexpr (I < NOPS) {
        constexpr int K = OPS.kind[I];
        constexpr int A = OPS.a[I];
        if constexpr (K == 3) {
            constexpr int B = OPS.b[I];
            gate_cnot<A, B>(re, im, lane);
        } else {
            float c = g_c[I], s = g_s[I];
            if constexpr (K == 0)      gate_rx<A>(re, im, c, s, lane);
            else if constexpr (K == 1) gate_ry<A>(re, im, c, s, lane);
            else                       gate_rz<A>(re, im, c, s, lane);
        }
        run_ops<I + 1>(re, im, lane);
    }
}

template<int W>
__device__ __forceinline__ void run_final(float (&re)[32], float (&im)[32], int lane,
                                          float crx, float srx, float cry, float sry) {
    if constexpr (W < NW) {
        gate_rx<W>(re, im, crx, srx, lane);
        gate_ry<W>(re, im, cry, sry, lane);
        run_final<W + 1>(re, im, lane, crx, srx, cry, sry);
    }
}

__device__ __forceinline__ float wsum(float v) {
    v += __shfl_xor_sync(FULLM, v, 16);
    v += __shfl_xor_sync(FULLM, v, 8);
    v += __shfl_xor_sync(FULLM, v, 4);
    v += __shfl_xor_sync(FULLM, v, 2);
    v += __shfl_xor_sync(FULLM, v, 1);
    return v;
}

// ============================================================================
// Main kernel: one warp per batch element, full state in registers.
// ============================================================================
__global__ void __launch_bounds__(128)
qsim_kernel(const float* __restrict__ x, const float* __restrict__ head_w,
            float* __restrict__ out, int bsz) {
    int warp = (int)((blockIdx.x * blockDim.x + threadIdx.x) >> 5);
    int lane = (int)(threadIdx.x & 31);
    if (warp >= bsz) return;

    // ---- encoder: product state of RY(x_w)|0> ----
    const float* xr = x + warp * NW;
    float xq[NW], cs[NW], sn[NW];
    #pragma unroll
    for (int w = 0; w < NW; ++w) {
        xq[w] = xr[w];
        sincosf(0.5f * xq[w], &sn[w], &cs[w]);
    }
    float pl = 1.0f;
    #pragma unroll
    for (int w = 0; w < 5; ++w) pl *= ((lane >> w) & 1) ? sn[w] : cs[w];

    float re[32], im[32];
    #pragma unroll
    for (int r = 0; r < 32; ++r) {
        float pr = pl;
        #pragma unroll
        for (int j = 0; j < 5; ++j) pr *= ((r >> j) & 1) ? sn[5 + j] : cs[5 + j];
        re[r] = pr;
        im[r] = 0.0f;
    }

    // ---- 30 frozen random gates ----
    run_ops<0>(re, im, lane);

    // ---- shared RX then RY on every wire ----
    {
        float crx = g_frx[0], srx = g_frx[1];
        float cry = g_fry[0], sry = g_fry[1];
        run_final<0>(re, im, lane, crx, srx, cry, sry);
    }

    // ---- measurement: <Z_w> ----
    float tot = 0.f, z5 = 0.f, z6 = 0.f, z7 = 0.f, z8 = 0.f, z9 = 0.f;
    #pragma unroll
    for (int r = 0; r < 32; ++r) {
        float p = re[r] * re[r] + im[r] * im[r];
        tot += p;
        z5 += (r & 1)  ? -p : p;
        z6 += (r & 2)  ? -p : p;
        z7 += (r & 4)  ? -p : p;
        z8 += (r & 8)  ? -p : p;
        z9 += (r & 16) ? -p : p;
    }
    z5 = wsum(z5); z6 = wsum(z6); z7 = wsum(z7); z8 = wsum(z8); z9 = wsum(z9);
    float z0 = wsum(((lane >> 0) & 1) ? -tot : tot);
    float z1 = wsum(((lane >> 1) & 1) ? -tot : tot);
    float z2 = wsum(((lane >> 2) & 1) ? -tot : tot);
    float z3 = wsum(((lane >> 3) & 1) ? -tot : tot);
    float z4 = wsum(((lane >> 4) & 1) ? -tot : tot);

    if (lane == 0) {
        float q = g_bias;
        q += z0 * head_w[0] + z1 * head_w[1] + z2 * head_w[2] + z3 * head_w[3] + z4 * head_w[4];
        q += z5 * head_w[5] + z6 * head_w[6] + z7 * head_w[7] + z8 * head_w[8] + z9 * head_w[9];
        #pragma unroll
        for (int w = 0; w < NW; ++w) q += xq[w] * g_u0[w];
        out[warp] = q;
    }
}

// ============================================================================
// Launch
// ============================================================================
extern "C" void kernel_launch(void* const* d_in, const int* in_sizes, int n_in,
                              void* d_out, int out_size) {
    const float* x   = (const float*)d_in[0];
    const float* rp  = (const float*)d_in[1];
    const float* rxt = (const float*)d_in[2];
    const float* ryt = (const float*)d_in[3];
    const float* hw  = (const float*)d_in[4];
    const float* hb  = (const float*)d_in[5];
    const float* w0  = (const float*)d_in[6];
    const float* b0  = (const float*)d_in[7];
    const float* w1  = (const float*)d_in[8];
    const float* b1  = (const float*)d_in[9];
    const float* w2  = (const float*)d_in[10];
    const float* b2  = (const float*)d_in[11];
    const float* w3  = (const float*)d_in[12];
    const float* b3  = (const float*)d_in[13];

    int bsz = in_sizes[0] / NW;

    prep_kernel<<<1, 64>>>(rp, rxt, ryt, hb, w0, b0, w1, b1, w2, b2, w3, b3);

    const int warps_per_block = 4;  // 128 threads
    int blocks = (bsz + warps_per_block - 1) / warps_per_block;
    qsim_kernel<<<blocks, 128>>>(x, hw, (float*)d_out, bsz);
}